// round 2
// baseline (speedup 1.0000x reference)
#include <cuda_runtime.h>
#include <cstdint>

// Problem dims
#define Bb     64
#define Nn     512
#define Tt     (Bb*Nn)        // 32768 tokens
#define DX     128
#define DIN    256
#define Hh     4096
#define Rr     1024

typedef unsigned long long ull;

// ---------------- device scratch (static: no allocations allowed) -----------
__device__ float g_h1[(size_t)Tt * Hh];     // 512 MB: layer-1 activations
__device__ float g_h2sum[(size_t)Bb * Hh];  // per-batch masked sum of h2
__device__ float g_maskf[Tt];               // normalized mask (0/1 fp32)
__device__ float g_cnt[Bb];                 // per-batch counts (>=1)
__device__ int   g_mtype;                   // 0=u8, 1=i32, 2=f32

// ---------------- f32x2 packed-FMA helpers (Blackwell) ----------------------
__device__ __forceinline__ ull pk2(float lo, float hi) {
    ull r; asm("mov.b64 %0,{%1,%2};" : "=l"(r) : "f"(lo), "f"(hi)); return r;
}
__device__ __forceinline__ void upk2(ull v, float& lo, float& hi) {
    asm("mov.b64 {%0,%1},%2;" : "=f"(lo), "=f"(hi) : "l"(v));
}
__device__ __forceinline__ void fma2(ull& d, ull a, ull b) {
    asm("fma.rn.f32x2 %0,%1,%2,%0;" : "+l"(d) : "l"(a), "l"(b));
}

// ---------------- mask dtype detection --------------------------------------
// mask[b][0] == 1 for every b (length >= 1).  Probe words at byte offsets
// 0, 2048, 4096, 6144:
//   float32 buffer: these are rows 0..3 starts -> all 0x3F800000
//   int32 buffer  : rows 0..3 starts -> all integer 1
//   uint8 buffer  : rows 0,4,8,12 starts -> (1,m,m,m) byte packs, almost
//                   surely not all in {0,1} and never 0x3F800000.
__global__ void detect_mask_kernel(const unsigned int* m) {
    unsigned w0 = m[0], w1 = m[512], w2 = m[1024], w3 = m[1536];
    int t;
    if (w0 == 0x3F800000u && w1 == 0x3F800000u && w2 == 0x3F800000u && w3 == 0x3F800000u)
        t = 2;
    else if (w0 <= 1u && w1 <= 1u && w2 <= 1u && w3 <= 1u)
        t = 1;
    else
        t = 0;
    g_mtype = t;
}

// One block per batch row: normalize mask to f32, count, zero h2sum.
__global__ void normalize_mask_kernel(const void* mask) {
    __shared__ float red[512];
    int b = blockIdx.x, n = threadIdx.x;
    int t = g_mtype;
    float v;
    size_t idx = (size_t)b * Nn + n;
    if (t == 0)      v = ((const unsigned char*)mask)[idx] ? 1.f : 0.f;
    else if (t == 1) v = ((const int*)mask)[idx] ? 1.f : 0.f;
    else             v = (((const float*)mask)[idx] != 0.f) ? 1.f : 0.f;
    g_maskf[idx] = v;
    red[n] = v;
    __syncthreads();
    for (int s = 256; s > 0; s >>= 1) {
        if (n < s) red[n] += red[n + s];
        __syncthreads();
    }
    if (n == 0) g_cnt[b] = fmaxf(red[0], 1.f);
    // zero accumulation buffer for layer-2 reduction
    #pragma unroll
    for (int j = 0; j < 8; j++)
        g_h2sum[(size_t)b * Hh + n + 512 * j] = 0.f;
}

// ---------------- GEMM tiling constants -------------------------------------
#define BM 128
#define BN 128
#define BK 16
#define ASTRIDE (BM + 4)   // 132, padded for bank spread

// ============================================================================
// Layer 1: h1 = relu([x|y] @ W1 + b1)     M=T, K=256, N=H
// ============================================================================
__global__ __launch_bounds__(256, 2)
void gemm1_kernel(const float* __restrict__ x, const float* __restrict__ y,
                  const float* __restrict__ W1, const float* __restrict__ b1) {
    int n0 = blockIdx.x * BN;
    int t0 = blockIdx.y * BM;
    if (g_maskf[t0] == 0.f) return;   // whole token tile masked (prefix mask)

    __shared__ float As[BK * ASTRIDE];
    __shared__ float Bs[BK * BN];

    int tid = threadIdx.x;
    int tx = tid & 15, ty = tid >> 4;
    int rowBase = ty * 8, colBase = tx * 8;

    ull acc[8][4];
    #pragma unroll
    for (int i = 0; i < 8; i++)
        #pragma unroll
        for (int j = 0; j < 4; j++) acc[i][j] = 0ULL;

    for (int k0 = 0; k0 < DIN; k0 += BK) {
        // A source: concat(x,y); a 16-wide k-tile lies entirely in x or y
        const float* Asrc = (k0 < DX) ? (x + (size_t)t0 * DX + k0)
                                      : (y + (size_t)t0 * DX + (k0 - DX));
        #pragma unroll
        for (int l = 0; l < 2; l++) {
            int idx = tid + l * 256;          // 512 float4 loads
            int r = idx >> 2, f4 = idx & 3;
            float4 v = *(const float4*)(Asrc + (size_t)r * DX + f4 * 4);
            As[(f4 * 4 + 0) * ASTRIDE + r] = v.x;
            As[(f4 * 4 + 1) * ASTRIDE + r] = v.y;
            As[(f4 * 4 + 2) * ASTRIDE + r] = v.z;
            As[(f4 * 4 + 3) * ASTRIDE + r] = v.w;
        }
        #pragma unroll
        for (int l = 0; l < 2; l++) {
            int idx = tid + l * 256;
            int r = idx >> 5, c4 = idx & 31;
            float4 v = *(const float4*)(W1 + (size_t)(k0 + r) * Hh + n0 + c4 * 4);
            *(float4*)&Bs[r * BN + c4 * 4] = v;
        }
        __syncthreads();
        #pragma unroll
        for (int kk = 0; kk < BK; kk++) {
            float4 a0 = *(const float4*)&As[kk * ASTRIDE + rowBase];
            float4 a1 = *(const float4*)&As[kk * ASTRIDE + rowBase + 4];
            ull a2[8];
            a2[0] = pk2(a0.x, a0.x); a2[1] = pk2(a0.y, a0.y);
            a2[2] = pk2(a0.z, a0.z); a2[3] = pk2(a0.w, a0.w);
            a2[4] = pk2(a1.x, a1.x); a2[5] = pk2(a1.y, a1.y);
            a2[6] = pk2(a1.z, a1.z); a2[7] = pk2(a1.w, a1.w);
            const ull* bp = (const ull*)&Bs[kk * BN + colBase];
            ull b0 = bp[0], b1r = bp[1], b2r = bp[2], b3r = bp[3];
            #pragma unroll
            for (int i = 0; i < 8; i++) {
                fma2(acc[i][0], a2[i], b0);
                fma2(acc[i][1], a2[i], b1r);
                fma2(acc[i][2], a2[i], b2r);
                fma2(acc[i][3], a2[i], b3r);
            }
        }
        __syncthreads();
    }

    // epilogue: bias + relu + store
    float4 bv0 = *(const float4*)&b1[n0 + colBase];
    float4 bv1 = *(const float4*)&b1[n0 + colBase + 4];
    float bias[8] = {bv0.x, bv0.y, bv0.z, bv0.w, bv1.x, bv1.y, bv1.z, bv1.w};
    #pragma unroll
    for (int i = 0; i < 8; i++) {
        float o[8];
        upk2(acc[i][0], o[0], o[1]);
        upk2(acc[i][1], o[2], o[3]);
        upk2(acc[i][2], o[4], o[5]);
        upk2(acc[i][3], o[6], o[7]);
        #pragma unroll
        for (int j = 0; j < 8; j++) o[j] = fmaxf(o[j] + bias[j], 0.f);
        float* dst = g_h1 + (size_t)(t0 + rowBase + i) * Hh + n0 + colBase;
        *(float4*)dst       = make_float4(o[0], o[1], o[2], o[3]);
        *(float4*)(dst + 4) = make_float4(o[4], o[5], o[6], o[7]);
    }
}

// ============================================================================
// Layer 2: h2 = relu(h1 @ W2 + b2), then masked column-sum into g_h2sum
//          M=T, K=H, N=H
// ============================================================================
__global__ __launch_bounds__(256, 2)
void gemm2_kernel(const float* __restrict__ W2, const float* __restrict__ b2) {
    int n0 = blockIdx.x * BN;
    int t0 = blockIdx.y * BM;
    if (g_maskf[t0] == 0.f) return;

    __shared__ float As[BK * ASTRIDE];
    __shared__ float Bs[BK * BN];
    __shared__ float colsum[BN];

    int tid = threadIdx.x;
    int tx = tid & 15, ty = tid >> 4;
    int rowBase = ty * 8, colBase = tx * 8;

    ull acc[8][4];
    #pragma unroll
    for (int i = 0; i < 8; i++)
        #pragma unroll
        for (int j = 0; j < 4; j++) acc[i][j] = 0ULL;

    const float* Abase = g_h1 + (size_t)t0 * Hh;

    for (int k0 = 0; k0 < Hh; k0 += BK) {
        #pragma unroll
        for (int l = 0; l < 2; l++) {
            int idx = tid + l * 256;
            int r = idx >> 2, f4 = idx & 3;
            float4 v = *(const float4*)(Abase + (size_t)r * Hh + k0 + f4 * 4);
            As[(f4 * 4 + 0) * ASTRIDE + r] = v.x;
            As[(f4 * 4 + 1) * ASTRIDE + r] = v.y;
            As[(f4 * 4 + 2) * ASTRIDE + r] = v.z;
            As[(f4 * 4 + 3) * ASTRIDE + r] = v.w;
        }
        #pragma unroll
        for (int l = 0; l < 2; l++) {
            int idx = tid + l * 256;
            int r = idx >> 5, c4 = idx & 31;
            float4 v = *(const float4*)(W2 + (size_t)(k0 + r) * Hh + n0 + c4 * 4);
            *(float4*)&Bs[r * BN + c4 * 4] = v;
        }
        __syncthreads();
        #pragma unroll
        for (int kk = 0; kk < BK; kk++) {
            float4 a0 = *(const float4*)&As[kk * ASTRIDE + rowBase];
            float4 a1 = *(const float4*)&As[kk * ASTRIDE + rowBase + 4];
            ull a2[8];
            a2[0] = pk2(a0.x, a0.x); a2[1] = pk2(a0.y, a0.y);
            a2[2] = pk2(a0.z, a0.z); a2[3] = pk2(a0.w, a0.w);
            a2[4] = pk2(a1.x, a1.x); a2[5] = pk2(a1.y, a1.y);
            a2[6] = pk2(a1.z, a1.z); a2[7] = pk2(a1.w, a1.w);
            const ull* bp = (const ull*)&Bs[kk * BN + colBase];
            ull b0 = bp[0], b1r = bp[1], b2r = bp[2], b3r = bp[3];
            #pragma unroll
            for (int i = 0; i < 8; i++) {
                fma2(acc[i][0], a2[i], b0);
                fma2(acc[i][1], a2[i], b1r);
                fma2(acc[i][2], a2[i], b2r);
                fma2(acc[i][3], a2[i], b3r);
            }
        }
        __syncthreads();
    }

    // epilogue: relu(acc+b2), weight by token mask, reduce columns
    float4 bv0 = *(const float4*)&b2[n0 + colBase];
    float4 bv1 = *(const float4*)&b2[n0 + colBase + 4];
    float bias[8] = {bv0.x, bv0.y, bv0.z, bv0.w, bv1.x, bv1.y, bv1.z, bv1.w};
    float p[8] = {0, 0, 0, 0, 0, 0, 0, 0};
    #pragma unroll
    for (int i = 0; i < 8; i++) {
        float rm = g_maskf[t0 + rowBase + i];
        float o[8];
        upk2(acc[i][0], o[0], o[1]);
        upk2(acc[i][1], o[2], o[3]);
        upk2(acc[i][2], o[4], o[5]);
        upk2(acc[i][3], o[6], o[7]);
        #pragma unroll
        for (int j = 0; j < 8; j++)
            p[j] += rm * fmaxf(o[j] + bias[j], 0.f);
    }
    if (tid < BN) colsum[tid] = 0.f;
    __syncthreads();
    #pragma unroll
    for (int j = 0; j < 8; j++)
        atomicAdd(&colsum[colBase + j], p[j]);
    __syncthreads();
    if (tid < BN) {
        int bb = t0 / Nn;   // 128-token tile lies in a single batch (512/128=4)
        atomicAdd(&g_h2sum[(size_t)bb * Hh + n0 + tid], colsum[tid]);
    }
}

// ============================================================================
// Layer 3 (tiny): out = (h2sum/count) @ W3 + b3      M=64, K=4096, N=1024
// ============================================================================
__global__ void out_init_kernel(float* __restrict__ out, const float* __restrict__ b3) {
    int b = blockIdx.x, r = threadIdx.x;
    #pragma unroll
    for (int j = 0; j < 4; j++)
        out[(size_t)b * Rr + r + 256 * j] = b3[r + 256 * j];
}

__global__ __launch_bounds__(256)
void out_gemm_kernel(const float* __restrict__ W3, float* __restrict__ out) {
    __shared__ float As[Bb * 128];       // 32 KB: scaled h2sum slice
    int rt = blockIdx.x * 128;
    int k0 = blockIdx.y * 128;
    int tid = threadIdx.x;

    #pragma unroll
    for (int l = 0; l < 32; l++) {
        int idx = tid + l * 256;
        int b = idx >> 7, k = idx & 127;
        As[b * 128 + k] = g_h2sum[(size_t)b * Hh + k0 + k] / g_cnt[b];
    }
    __syncthreads();

    int c = tid & 127, bg = tid >> 7;    // bg in {0,1}: 32 batches each
    float acc[32];
    #pragma unroll
    for (int i = 0; i < 32; i++) acc[i] = 0.f;

    for (int k = 0; k < 128; k++) {
        float w = W3[(size_t)(k0 + k) * Rr + rt + c];
        #pragma unroll
        for (int i = 0; i < 32; i++)
            acc[i] += As[(bg * 32 + i) * 128 + k] * w;
    }
    #pragma unroll
    for (int i = 0; i < 32; i++)
        atomicAdd(&out[(size_t)(bg * 32 + i) * Rr + rt + c], acc[i]);
}

// ============================================================================
extern "C" void kernel_launch(void* const* d_in, const int* in_sizes, int n_in,
                              void* d_out, int out_size) {
    const float* x  = (const float*)d_in[0];
    const float* y  = (const float*)d_in[1];
    const void*  mk = d_in[2];
    const float* W1 = (const float*)d_in[3];
    const float* b1 = (const float*)d_in[4];
    const float* W2 = (const float*)d_in[5];
    const float* b2 = (const float*)d_in[6];
    const float* W3 = (const float*)d_in[7];
    const float* b3 = (const float*)d_in[8];
    float* out = (float*)d_out;

    detect_mask_kernel<<<1, 1>>>((const unsigned int*)mk);
    normalize_mask_kernel<<<Bb, Nn>>>(mk);
    gemm1_kernel<<<dim3(Hh / BN, Tt / BM), 256>>>(x, y, W1, b1);
    gemm2_kernel<<<dim3(Hh / BN, Tt / BM), 256>>>(W2, b2);
    out_init_kernel<<<Bb, 256>>>(out, b3);
    out_gemm_kernel<<<dim3(Rr / 128, Hh / 128), 256>>>(W3, out);
}